// round 1
// baseline (speedup 1.0000x reference)
#include <cuda_runtime.h>

// RBF kernel matrix: out[i,j] = v * exp(-0.5 * || X[i]/l - X2[j]/l ||^2)
// N = M = 8192, D = 64.
// Strategy: fused GEMM-form: cross = Xl @ X2l^T on CUDA cores with packed
// fp32x2 FMA; norms precomputed into device scratch; epilogue fuses
// exp2(LOG2E * (cross - hx - hy)) * v.

#define NROWS 8192
#define MROWS 8192
#define DDIM  64

// Scratch (allocation-free rule: __device__ globals)
__device__ float g_invl[DDIM];
__device__ float g_v;
__device__ float g_hxn[NROWS];
__device__ float g_hyn[MROWS];

// ---------------------------------------------------------------------------
// packed f32x2 helpers (Blackwell sm_103a)
// ---------------------------------------------------------------------------
__device__ __forceinline__ unsigned long long packf2(float lo, float hi) {
    unsigned long long r;
    asm("mov.b64 %0, {%1, %2};"
        : "=l"(r) : "r"(__float_as_uint(lo)), "r"(__float_as_uint(hi)));
    return r;
}
__device__ __forceinline__ unsigned long long dup2(float x) {
    unsigned long long r;
    unsigned int u = __float_as_uint(x);
    asm("mov.b64 %0, {%1, %1};" : "=l"(r) : "r"(u));
    return r;
}
__device__ __forceinline__ void ffma2(unsigned long long& d,
                                      unsigned long long a,
                                      unsigned long long b) {
    asm("fma.rn.f32x2 %0, %1, %2, %0;" : "+l"(d) : "l"(a), "l"(b));
}
__device__ __forceinline__ void unpack2(unsigned long long p, float& lo, float& hi) {
    unsigned int a, b;
    asm("mov.b64 {%0, %1}, %2;" : "=r"(a), "=r"(b) : "l"(p));
    lo = __uint_as_float(a);
    hi = __uint_as_float(b);
}
__device__ __forceinline__ float fexp2(float x) {
    float r;
    asm("ex2.approx.f32 %0, %1;" : "=f"(r) : "f"(x));
    return r;
}

// ---------------------------------------------------------------------------
// Prep: softplus params + half squared norms of scaled rows
// ---------------------------------------------------------------------------
__global__ void prep_kernel(const float* __restrict__ X,
                            const float* __restrict__ X2,
                            const float* __restrict__ ls,
                            const float* __restrict__ var) {
    __shared__ float invl_s[DDIM];
    int t = threadIdx.x;
    if (t < DDIM) {
        float r = ls[t];
        // softplus, stable: max(r,0) + log1p(exp(-|r|))
        float l = fmaxf(r, 0.0f) + log1pf(expf(-fabsf(r)));
        float il = 1.0f / l;
        invl_s[t] = il;
        if (blockIdx.x == 0) g_invl[t] = il;
    }
    if (blockIdx.x == 0 && t == 64) {
        float r = var[0];
        g_v = fmaxf(r, 0.0f) + log1pf(expf(-fabsf(r)));
    }
    __syncthreads();

    int warp = t >> 5, lane = t & 31;
    int nwarps = blockDim.x >> 5;
    for (int row = blockIdx.x * nwarps + warp; row < NROWS + MROWS;
         row += gridDim.x * nwarps) {
        const float* src = (row < NROWS) ? (X + (size_t)row * DDIM)
                                         : (X2 + (size_t)(row - NROWS) * DDIM);
        float s = 0.0f;
        #pragma unroll
        for (int j = 0; j < 2; j++) {
            int d = lane + 32 * j;
            float x = src[d] * invl_s[d];
            s = fmaf(x, x, s);
        }
        #pragma unroll
        for (int off = 16; off; off >>= 1)
            s += __shfl_xor_sync(0xffffffffu, s, off);
        if (lane == 0) {
            if (row < NROWS) g_hxn[row] = 0.5f * s;
            else             g_hyn[row - NROWS] = 0.5f * s;
        }
    }
}

// ---------------------------------------------------------------------------
// Main: 128x128 tile per 256-thread CTA, 8x8 per-thread outputs.
// Smem tiles [128 rows][64 k] fp32, XOR swizzle on 16B chunks:
//   phys_chunk = c4 ^ ((row>>3) & 7)
// ---------------------------------------------------------------------------
__global__ void __launch_bounds__(256)
rbf_main_kernel(const float* __restrict__ X,
                const float* __restrict__ X2,
                float* __restrict__ out) {
    extern __shared__ float sm[];
    float* As = sm;                 // 128*64 floats (32 KB)
    float* Bs = sm + 128 * 64;      // 128*64 floats (32 KB)

    const int t = threadIdx.x;
    const int row0 = blockIdx.y * 128;   // X rows
    const int col0 = blockIdx.x * 128;   // X2 rows

    const int c4 = t & 15;          // float4 column (k-chunk), fixed per thread
    const int rbase = t >> 4;       // base row

    float4 il = reinterpret_cast<const float4*>(g_invl)[c4];

    float4* A4 = reinterpret_cast<float4*>(As);
    float4* B4 = reinterpret_cast<float4*>(Bs);

    // Fill both tiles (coalesced global reads, swizzled smem writes)
    #pragma unroll
    for (int it = 0; it < 8; it++) {
        int r = rbase + it * 16;
        int sw = c4 ^ ((r >> 3) & 7);
        float4 va = reinterpret_cast<const float4*>(X + (size_t)(row0 + r) * DDIM)[c4];
        va.x *= il.x; va.y *= il.y; va.z *= il.z; va.w *= il.w;
        A4[r * 16 + sw] = va;
        float4 vb = reinterpret_cast<const float4*>(X2 + (size_t)(col0 + r) * DDIM)[c4];
        vb.x *= il.x; vb.y *= il.y; vb.z *= il.z; vb.w *= il.w;
        B4[r * 16 + sw] = vb;
    }
    __syncthreads();

    const int tx = t & 15;          // column group: n = tx*8 .. tx*8+7
    const int ty = t >> 4;          // row group:    m = ty*8 .. ty*8+7

    // packed accumulators: acc[i][jp] holds outputs (m=ty*8+i, n=tx*8+2jp, +1)
    unsigned long long acc[8][4];
    #pragma unroll
    for (int i = 0; i < 8; i++)
        #pragma unroll
        for (int jp = 0; jp < 4; jp++)
            acc[i][jp] = 0ULL;

    #pragma unroll 2
    for (int k4 = 0; k4 < 16; k4++) {
        float a_s[8][4];
        float b_s[8][4];
        #pragma unroll
        for (int i = 0; i < 8; i++) {
            int m = ty * 8 + i;
            *reinterpret_cast<float4*>(&a_s[i][0]) =
                A4[m * 16 + (k4 ^ ((m >> 3) & 7))];
        }
        #pragma unroll
        for (int j = 0; j < 8; j++) {
            int n = tx * 8 + j;
            *reinterpret_cast<float4*>(&b_s[j][0]) =
                B4[n * 16 + (k4 ^ ((n >> 3) & 7))];
        }
        #pragma unroll
        for (int kk = 0; kk < 4; kk++) {
            unsigned long long bp[4];
            #pragma unroll
            for (int jp = 0; jp < 4; jp++)
                bp[jp] = packf2(b_s[2 * jp][kk], b_s[2 * jp + 1][kk]);
            #pragma unroll
            for (int i = 0; i < 8; i++) {
                unsigned long long ad = dup2(a_s[i][kk]);
                #pragma unroll
                for (int jp = 0; jp < 4; jp++)
                    ffma2(acc[i][jp], ad, bp[jp]);
            }
        }
    }

    // Epilogue: out = v * exp2(LOG2E * min(cross - hx - hy, 0))
    const float L2E = 1.4426950408889634f;
    float v = g_v;
    float hy[8];
    #pragma unroll
    for (int j = 0; j < 8; j++) hy[j] = g_hyn[col0 + tx * 8 + j];

    #pragma unroll
    for (int i = 0; i < 8; i++) {
        int gm = row0 + ty * 8 + i;
        float hx = g_hxn[gm];
        float o[8];
        #pragma unroll
        for (int jp = 0; jp < 4; jp++)
            unpack2(acc[i][jp], o[2 * jp], o[2 * jp + 1]);
        #pragma unroll
        for (int j = 0; j < 8; j++) {
            float e = o[j] - hx - hy[j];
            e = fminf(e, 0.0f);             // d2 clamp (>=0)
            o[j] = v * fexp2(e * L2E);
        }
        float* op = out + (size_t)gm * MROWS + col0 + tx * 8;
        reinterpret_cast<float4*>(op)[0] =
            make_float4(o[0], o[1], o[2], o[3]);
        reinterpret_cast<float4*>(op)[1] =
            make_float4(o[4], o[5], o[6], o[7]);
    }
}

// ---------------------------------------------------------------------------
extern "C" void kernel_launch(void* const* d_in, const int* in_sizes, int n_in,
                              void* d_out, int out_size) {
    const float* X   = (const float*)d_in[0];
    const float* X2  = (const float*)d_in[1];
    const float* ls  = (const float*)d_in[2];
    const float* var = (const float*)d_in[3];
    float* out = (float*)d_out;

    prep_kernel<<<256, 256>>>(X, X2, ls, var);

    cudaFuncSetAttribute(rbf_main_kernel,
                         cudaFuncAttributeMaxDynamicSharedMemorySize, 65536);
    dim3 grid(MROWS / 128, NROWS / 128);
    rbf_main_kernel<<<grid, 256, 65536>>>(X, X2, out);
}

// round 3
// speedup vs baseline: 2.5836x; 2.5836x over previous
#include <cuda_runtime.h>
#include <cuda_bf16.h>
#include <cstdint>

// RBF kernel matrix: out[i,j] = v * exp(min(cross_ij - hx_i - hy_j, 0))
// cross via classic mma.sync m16n8k16 bf16, 3-term hi/lo split
// (hi*hi + hi*lo + lo*hi). N = M = 8192, D = 64. Output fp32 [N, M].

#define NROWS 8192
#define MROWS 8192
#define DDIM  64

// ---------------- device scratch (allocation-free rule) ----------------
__device__ float g_invl[DDIM];
__device__ float g_v;
__device__ float g_hxn[NROWS];                    // 0.5*||Xl_i||^2
__device__ float g_hyn[MROWS];                    // 0.5*||X2l_j||^2
__device__ __nv_bfloat16 g_Xhi[NROWS * DDIM];
__device__ __nv_bfloat16 g_Xlo[NROWS * DDIM];
__device__ __nv_bfloat16 g_Yhi[MROWS * DDIM];
__device__ __nv_bfloat16 g_Ylo[MROWS * DDIM];

// ---------------- helpers ----------------
__device__ __forceinline__ uint32_t smem_u32(const void* p) {
    uint32_t a;
    asm("{ .reg .u64 t; cvta.to.shared.u64 t, %1; cvt.u32.u64 %0, t; }"
        : "=r"(a) : "l"(p));
    return a;
}

__device__ __forceinline__ void ldsm_x4(uint32_t& r0, uint32_t& r1,
                                        uint32_t& r2, uint32_t& r3,
                                        uint32_t addr) {
    asm volatile("ldmatrix.sync.aligned.m8n8.x4.shared.b16 {%0,%1,%2,%3}, [%4];"
                 : "=r"(r0), "=r"(r1), "=r"(r2), "=r"(r3) : "r"(addr));
}

__device__ __forceinline__ void mma_bf16(float* c, const uint32_t* a,
                                         uint32_t b0, uint32_t b1) {
    asm volatile(
        "mma.sync.aligned.m16n8k16.row.col.f32.bf16.bf16.f32 "
        "{%0,%1,%2,%3}, {%4,%5,%6,%7}, {%8,%9}, {%0,%1,%2,%3};"
        : "+f"(c[0]), "+f"(c[1]), "+f"(c[2]), "+f"(c[3])
        : "r"(a[0]), "r"(a[1]), "r"(a[2]), "r"(a[3]), "r"(b0), "r"(b1));
}

__device__ __forceinline__ float fexp2(float x) {
    float r;
    asm("ex2.approx.f32 %0, %1;" : "=f"(r) : "f"(x));
    return r;
}

// ---------------------------------------------------------------------------
// Prep: softplus params, bf16 hi/lo split of scaled rows, half squared norms
// ---------------------------------------------------------------------------
__global__ void prep_kernel(const float* __restrict__ X,
                            const float* __restrict__ X2,
                            const float* __restrict__ ls,
                            const float* __restrict__ var) {
    __shared__ float invl_s[DDIM];
    int t = threadIdx.x;
    if (t < DDIM) {
        float r = ls[t];
        float l = fmaxf(r, 0.0f) + log1pf(expf(-fabsf(r)));
        float il = 1.0f / l;
        invl_s[t] = il;
        if (blockIdx.x == 0) g_invl[t] = il;
    }
    if (blockIdx.x == 0 && t == 64) {
        float r = var[0];
        g_v = fmaxf(r, 0.0f) + log1pf(expf(-fabsf(r)));
    }
    __syncthreads();

    int warp = t >> 5, lane = t & 31;
    int nwarps = blockDim.x >> 5;
    for (int row = blockIdx.x * nwarps + warp; row < NROWS + MROWS;
         row += gridDim.x * nwarps) {
        const float* src;
        __nv_bfloat16 *hi, *lo;
        int r;
        bool isX = (row < NROWS);
        if (isX) { r = row;         src = X  + (size_t)r * DDIM; hi = g_Xhi; lo = g_Xlo; }
        else     { r = row - NROWS; src = X2 + (size_t)r * DDIM; hi = g_Yhi; lo = g_Ylo; }
        float s = 0.0f;
        #pragma unroll
        for (int j = 0; j < 2; j++) {
            int d = lane + 32 * j;
            float xl = src[d] * invl_s[d];
            __nv_bfloat16 bh = __float2bfloat16(xl);
            __nv_bfloat16 bl = __float2bfloat16(xl - __bfloat162float(bh));
            hi[(size_t)r * DDIM + d] = bh;
            lo[(size_t)r * DDIM + d] = bl;
            s = fmaf(xl, xl, s);
        }
        #pragma unroll
        for (int off = 16; off; off >>= 1)
            s += __shfl_xor_sync(0xffffffffu, s, off);
        if (lane == 0) {
            if (isX) g_hxn[r] = 0.5f * s;
            else     g_hyn[r] = 0.5f * s;
        }
    }
}

// ---------------------------------------------------------------------------
// Main: 128x128 output tile per 256-thread CTA. 8 warps in 2(m) x 4(n) grid,
// each warp computes 64x32 via mma.sync m16n8k16 (4 m-tiles x 4 n-tiles).
// Smem tiles: [128 rows][64 bf16] = 128B rows, 16B-chunk XOR swizzle
//   phys_chunk = c ^ (row & 7)    -> ldmatrix conflict-free.
// ---------------------------------------------------------------------------
#define SMEM_HX    0                   // 128 floats
#define SMEM_HY    512                 // 128 floats
#define SMEM_TILES 1024                // Xhi, Xlo, Yhi, Ylo: 16 KB each
#define TILE_BYTES 16384
#define SMEM_TOTAL (1024 + 4 * TILE_BYTES)

__global__ void __launch_bounds__(256, 2)
rbf_mma_kernel(float* __restrict__ out) {
    extern __shared__ char smem[];
    const uint32_t sb = smem_u32(smem);
    const int t = threadIdx.x;
    const int wid = t >> 5;
    const int lane = t & 31;

    const int x0 = blockIdx.y * 128;      // X rows (output rows)
    const int y0 = blockIdx.x * 128;      // X2 rows (output cols)

    // Norm tiles
    if (t < 128)      ((float*)(smem + SMEM_HX))[t]       = g_hxn[x0 + t];
    else              ((float*)(smem + SMEM_HY))[t - 128] = g_hyn[y0 + (t - 128)];

    // Fill 4 bf16 tiles with swizzle (each thread: 4 uint4 per tile)
    {
        const uint4* srcs[4] = {
            (const uint4*)(g_Xhi + (size_t)x0 * DDIM),
            (const uint4*)(g_Xlo + (size_t)x0 * DDIM),
            (const uint4*)(g_Yhi + (size_t)y0 * DDIM),
            (const uint4*)(g_Ylo + (size_t)y0 * DDIM)
        };
        #pragma unroll
        for (int tile = 0; tile < 4; tile++) {
            char* dst = smem + SMEM_TILES + tile * TILE_BYTES;
            #pragma unroll
            for (int i = 0; i < 4; i++) {
                int id = t + i * 256;               // chunk id: row*8 + c
                int row = id >> 3, c = id & 7;
                uint32_t sw = (uint32_t)row * 128 + (uint32_t)((c ^ (row & 7)) * 16);
                *(uint4*)(dst + sw) = srcs[tile][id];
            }
        }
    }
    __syncthreads();

    const uint32_t sXhi = sb + SMEM_TILES;
    const uint32_t sXlo = sXhi + TILE_BYTES;
    const uint32_t sYhi = sXlo + TILE_BYTES;
    const uint32_t sYlo = sYhi + TILE_BYTES;

    const int wy = wid & 1;               // m group: 64 rows
    const int wx = wid >> 1;              // n group: 32 cols

    // ldmatrix per-lane addressing: row-in-16 = lane&15, k-half = lane>>4
    const int lrow = lane & 15;
    const int lhalf = lane >> 4;
    const int lsw = lrow & 7;

    float acc[4][4][4];
    #pragma unroll
    for (int mt = 0; mt < 4; mt++)
        #pragma unroll
        for (int nt = 0; nt < 4; nt++)
            #pragma unroll
            for (int f = 0; f < 4; f++)
                acc[mt][nt][f] = 0.0f;

    const int mbase = wy * 64;
    const int nbase = wx * 32;

    #pragma unroll
    for (int term = 0; term < 3; term++) {
        const uint32_t At = (term == 2) ? sXlo : sXhi;
        const uint32_t Bt = (term == 1) ? sYlo : sYhi;
        #pragma unroll
        for (int kb = 0; kb < 4; kb++) {
            const uint32_t kchunk = (uint32_t)((kb * 2 + lhalf) ^ lsw) * 16;
            // B fragments: two ldmatrix.x4, covering n = nbase..nbase+31
            uint32_t bf[2][4];
            #pragma unroll
            for (int bp = 0; bp < 2; bp++) {
                uint32_t addr = Bt + (uint32_t)(nbase + bp * 16 + lrow) * 128 + kchunk;
                ldsm_x4(bf[bp][0], bf[bp][1], bf[bp][2], bf[bp][3], addr);
            }
            // A fragments + mma
            #pragma unroll
            for (int mt = 0; mt < 4; mt++) {
                uint32_t af[4];
                uint32_t addr = At + (uint32_t)(mbase + mt * 16 + lrow) * 128 + kchunk;
                ldsm_x4(af[0], af[1], af[2], af[3], addr);
                mma_bf16(acc[mt][0], af, bf[0][0], bf[0][2]);
                mma_bf16(acc[mt][1], af, bf[0][1], bf[0][3]);
                mma_bf16(acc[mt][2], af, bf[1][0], bf[1][2]);
                mma_bf16(acc[mt][3], af, bf[1][1], bf[1][3]);
            }
        }
    }

    // Epilogue: out = v * exp2(L2E * min(cross - hx - hy, 0)), fused in regs.
    const float L2E = 1.4426950408889634f;
    const float v = g_v;
    const int g = lane >> 2;
    const int n2 = (lane & 3) * 2;
    const float* HX = (const float*)(smem + SMEM_HX);
    const float* HY = (const float*)(smem + SMEM_HY);

    #pragma unroll
    for (int mt = 0; mt < 4; mt++) {
        const int r0 = mbase + mt * 16 + g;      // within tile
        const float hx0 = HX[r0];
        const float hx1 = HX[r0 + 8];
        #pragma unroll
        for (int nt = 0; nt < 4; nt++) {
            const int cc = nbase + nt * 8 + n2;
            const float hy0 = HY[cc];
            const float hy1 = HY[cc + 1];
            float* c = acc[mt][nt];
            float2 o0, o1;
            o0.x = v * fexp2(fminf(c[0] - hx0 - hy0, 0.0f) * L2E);
            o0.y = v * fexp2(fminf(c[1] - hx0 - hy1, 0.0f) * L2E);
            o1.x = v * fexp2(fminf(c[2] - hx1 - hy0, 0.0f) * L2E);
            o1.y = v * fexp2(fminf(c[3] - hx1 - hy1, 0.0f) * L2E);
            *(float2*)(out + (size_t)(x0 + r0) * MROWS + y0 + cc)     = o0;
            *(float2*)(out + (size_t)(x0 + r0 + 8) * MROWS + y0 + cc) = o1;
        }
    }
}

// ---------------------------------------------------------------------------
extern "C" void kernel_launch(void* const* d_in, const int* in_sizes, int n_in,
                              void* d_out, int out_size) {
    const float* X   = (const float*)d_in[0];
    const float* X2  = (const float*)d_in[1];
    const float* ls  = (const float*)d_in[2];
    const float* var = (const float*)d_in[3];
    float* out = (float*)d_out;

    prep_kernel<<<256, 256>>>(X, X2, ls, var);

    cudaFuncSetAttribute(rbf_mma_kernel,
                         cudaFuncAttributeMaxDynamicSharedMemorySize, SMEM_TOTAL);
    dim3 grid(MROWS / 128, NROWS / 128);
    rbf_mma_kernel<<<grid, 256, SMEM_TOTAL>>>(out);
}

// round 4
// speedup vs baseline: 3.4380x; 1.3307x over previous
#include <cuda_runtime.h>
#include <cuda_bf16.h>
#include <cstdint>

// RBF kernel matrix: out[i,j] = v * exp(min(cross_ij - hx_i - hy_j, 0))
// cross via classic mma.sync m16n8k16 bf16, 3-term hi/lo split
// (hi*hi + hi*lo + lo*hi). N = M = 8192, D = 64. Output fp32 [N, M].

#define NROWS 8192
#define MROWS 8192
#define DDIM  64

// ---------------- device scratch (allocation-free rule) ----------------
__device__ float g_invl[DDIM];
__device__ float g_v;
__device__ float g_lv;                            // log2(v)
__device__ float g_hxn[NROWS];                    // 0.5*||Xl_i||^2
__device__ float g_hyn[MROWS];                    // 0.5*||X2l_j||^2
__device__ __nv_bfloat16 g_Xhi[NROWS * DDIM];
__device__ __nv_bfloat16 g_Xlo[NROWS * DDIM];
__device__ __nv_bfloat16 g_Yhi[MROWS * DDIM];
__device__ __nv_bfloat16 g_Ylo[MROWS * DDIM];

// ---------------- helpers ----------------
__device__ __forceinline__ uint32_t smem_u32(const void* p) {
    uint32_t a;
    asm("{ .reg .u64 t; cvta.to.shared.u64 t, %1; cvt.u32.u64 %0, t; }"
        : "=r"(a) : "l"(p));
    return a;
}

__device__ __forceinline__ void ldsm_x4(uint32_t& r0, uint32_t& r1,
                                        uint32_t& r2, uint32_t& r3,
                                        uint32_t addr) {
    asm volatile("ldmatrix.sync.aligned.m8n8.x4.shared.b16 {%0,%1,%2,%3}, [%4];"
                 : "=r"(r0), "=r"(r1), "=r"(r2), "=r"(r3) : "r"(addr));
}

__device__ __forceinline__ void mma_bf16(float* c, const uint32_t* a,
                                         uint32_t b0, uint32_t b1) {
    asm volatile(
        "mma.sync.aligned.m16n8k16.row.col.f32.bf16.bf16.f32 "
        "{%0,%1,%2,%3}, {%4,%5,%6,%7}, {%8,%9}, {%0,%1,%2,%3};"
        : "+f"(c[0]), "+f"(c[1]), "+f"(c[2]), "+f"(c[3])
        : "r"(a[0]), "r"(a[1]), "r"(a[2]), "r"(a[3]), "r"(b0), "r"(b1));
}

__device__ __forceinline__ float fexp2(float x) {
    float r;
    asm("ex2.approx.f32 %0, %1;" : "=f"(r) : "f"(x));
    return r;
}

#define CP_ASYNC16(dst, src) \
    asm volatile("cp.async.cg.shared.global [%0], [%1], 16;" \
                 :: "r"(dst), "l"(src) : "memory")
#define CP_COMMIT() asm volatile("cp.async.commit_group;" ::: "memory")
#define CP_WAIT0()  asm volatile("cp.async.wait_group 0;" ::: "memory")

// ---------------------------------------------------------------------------
// Prep: softplus params, bf16 hi/lo split of scaled rows, half squared norms
// ---------------------------------------------------------------------------
__global__ void prep_kernel(const float* __restrict__ X,
                            const float* __restrict__ X2,
                            const float* __restrict__ ls,
                            const float* __restrict__ var) {
    __shared__ float invl_s[DDIM];
    int t = threadIdx.x;
    if (t < DDIM) {
        float r = ls[t];
        float l = fmaxf(r, 0.0f) + log1pf(expf(-fabsf(r)));
        float il = 1.0f / l;
        invl_s[t] = il;
        if (blockIdx.x == 0) g_invl[t] = il;
    }
    if (blockIdx.x == 0 && t == 64) {
        float r = var[0];
        float v = fmaxf(r, 0.0f) + log1pf(expf(-fabsf(r)));
        g_v = v;
        g_lv = log2f(v);
    }
    __syncthreads();

    int warp = t >> 5, lane = t & 31;
    int nwarps = blockDim.x >> 5;
    for (int row = blockIdx.x * nwarps + warp; row < NROWS + MROWS;
         row += gridDim.x * nwarps) {
        const float* src;
        __nv_bfloat16 *hi, *lo;
        int r;
        bool isX = (row < NROWS);
        if (isX) { r = row;         src = X  + (size_t)r * DDIM; hi = g_Xhi; lo = g_Xlo; }
        else     { r = row - NROWS; src = X2 + (size_t)r * DDIM; hi = g_Yhi; lo = g_Ylo; }
        float s = 0.0f;
        #pragma unroll
        for (int j = 0; j < 2; j++) {
            int d = lane + 32 * j;
            float xl = src[d] * invl_s[d];
            __nv_bfloat16 bh = __float2bfloat16(xl);
            __nv_bfloat16 bl = __float2bfloat16(xl - __bfloat162float(bh));
            hi[(size_t)r * DDIM + d] = bh;
            lo[(size_t)r * DDIM + d] = bl;
            s = fmaf(xl, xl, s);
        }
        #pragma unroll
        for (int off = 16; off; off >>= 1)
            s += __shfl_xor_sync(0xffffffffu, s, off);
        if (lane == 0) {
            if (isX) g_hxn[r] = 0.5f * s;
            else     g_hyn[r] = 0.5f * s;
        }
    }
}

// ---------------------------------------------------------------------------
// Main: 128x128 output tile per 256-thread CTA. 8 warps in 2(m) x 4(n) grid,
// each warp computes 64x32 via mma.sync m16n8k16 (4 m-tiles x 4 n-tiles).
// Smem tiles: [128 rows][64 bf16] = 128B rows, 16B-chunk XOR swizzle
//   phys_chunk = c ^ (row & 7)    -> ldmatrix conflict-free.
// Fragments (hi & lo for A and B) loaded ONCE per k-chunk, reused by all
// 3 MMA terms.
// ---------------------------------------------------------------------------
#define SMEM_HX    0                   // 128 floats: hx*L2E - log2(v)
#define SMEM_HY    512                 // 128 floats: hy*L2E
#define SMEM_TILES 1024                // Xhi, Xlo, Yhi, Ylo: 16 KB each
#define TILE_BYTES 16384
#define SMEM_TOTAL (1024 + 4 * TILE_BYTES)

__global__ void __launch_bounds__(256, 2)
rbf_mma_kernel(float* __restrict__ out) {
    extern __shared__ char smem[];
    const uint32_t sb = smem_u32(smem);
    const int t = threadIdx.x;
    const int wid = t >> 5;
    const int lane = t & 31;

    const int x0 = blockIdx.y * 128;      // X rows (output rows)
    const int y0 = blockIdx.x * 128;      // X2 rows (output cols)

    const float L2E = 1.4426950408889634f;
    const float lv = g_lv;

    // Tile fill via cp.async (LDGSTS), swizzled
    {
        const uint4* srcs[4] = {
            (const uint4*)(g_Xhi + (size_t)x0 * DDIM),
            (const uint4*)(g_Xlo + (size_t)x0 * DDIM),
            (const uint4*)(g_Yhi + (size_t)y0 * DDIM),
            (const uint4*)(g_Ylo + (size_t)y0 * DDIM)
        };
        #pragma unroll
        for (int tile = 0; tile < 4; tile++) {
            uint32_t dstb = sb + SMEM_TILES + tile * TILE_BYTES;
            #pragma unroll
            for (int i = 0; i < 4; i++) {
                int id = t + i * 256;               // chunk id: row*8 + c
                int row = id >> 3, c = id & 7;
                uint32_t sw = (uint32_t)row * 128 + (uint32_t)((c ^ (row & 7)) * 16);
                CP_ASYNC16(dstb + sw, srcs[tile] + id);
            }
        }
        CP_COMMIT();
    }

    // Norm tiles (pre-scaled for folded epilogue)
    if (t < 128)  ((float*)(smem + SMEM_HX))[t]       = g_hxn[x0 + t] * L2E - lv;
    else          ((float*)(smem + SMEM_HY))[t - 128] = g_hyn[y0 + (t - 128)] * L2E;

    CP_WAIT0();
    __syncthreads();

    const uint32_t sXhi = sb + SMEM_TILES;
    const uint32_t sXlo = sXhi + TILE_BYTES;
    const uint32_t sYhi = sXlo + TILE_BYTES;
    const uint32_t sYlo = sYhi + TILE_BYTES;

    const int wy = wid & 1;               // m group: 64 rows
    const int wx = wid >> 1;              // n group: 32 cols
    const int mbase = wy * 64;
    const int nbase = wx * 32;

    // ldmatrix per-lane addressing
    const int lrow = lane & 15;
    const int lhalf = lane >> 4;
    const int lsw = lrow & 7;
    const uint32_t rowA = (uint32_t)(mbase + lrow) * 128;
    const uint32_t rowB = (uint32_t)(nbase + lrow) * 128;
    uint32_t kc[4];
    #pragma unroll
    for (int kb = 0; kb < 4; kb++)
        kc[kb] = (uint32_t)(((kb * 2 + lhalf) ^ lsw) * 16);

    float acc[4][4][4];
    #pragma unroll
    for (int mt = 0; mt < 4; mt++)
        #pragma unroll
        for (int nt = 0; nt < 4; nt++)
            #pragma unroll
            for (int f = 0; f < 4; f++)
                acc[mt][nt][f] = 0.0f;

    #pragma unroll
    for (int kb = 0; kb < 4; kb++) {
        const uint32_t k = kc[kb];
        uint32_t bh[2][4], bl[2][4], ah[4][4], al[4][4];
        #pragma unroll
        for (int bp = 0; bp < 2; bp++) {
            ldsm_x4(bh[bp][0], bh[bp][1], bh[bp][2], bh[bp][3],
                    sYhi + rowB + bp * 2048 + k);
            ldsm_x4(bl[bp][0], bl[bp][1], bl[bp][2], bl[bp][3],
                    sYlo + rowB + bp * 2048 + k);
        }
        #pragma unroll
        for (int mt = 0; mt < 4; mt++)
            ldsm_x4(ah[mt][0], ah[mt][1], ah[mt][2], ah[mt][3],
                    sXhi + rowA + mt * 2048 + k);

        // term hi*hi
        #pragma unroll
        for (int mt = 0; mt < 4; mt++) {
            mma_bf16(acc[mt][0], ah[mt], bh[0][0], bh[0][2]);
            mma_bf16(acc[mt][1], ah[mt], bh[0][1], bh[0][3]);
            mma_bf16(acc[mt][2], ah[mt], bh[1][0], bh[1][2]);
            mma_bf16(acc[mt][3], ah[mt], bh[1][1], bh[1][3]);
        }
        // load A-lo while hi*lo MMAs run
        #pragma unroll
        for (int mt = 0; mt < 4; mt++)
            ldsm_x4(al[mt][0], al[mt][1], al[mt][2], al[mt][3],
                    sXlo + rowA + mt * 2048 + k);
        // term hi*lo
        #pragma unroll
        for (int mt = 0; mt < 4; mt++) {
            mma_bf16(acc[mt][0], ah[mt], bl[0][0], bl[0][2]);
            mma_bf16(acc[mt][1], ah[mt], bl[0][1], bl[0][3]);
            mma_bf16(acc[mt][2], ah[mt], bl[1][0], bl[1][2]);
            mma_bf16(acc[mt][3], ah[mt], bl[1][1], bl[1][3]);
        }
        // term lo*hi
        #pragma unroll
        for (int mt = 0; mt < 4; mt++) {
            mma_bf16(acc[mt][0], al[mt], bh[0][0], bh[0][2]);
            mma_bf16(acc[mt][1], al[mt], bh[0][1], bh[0][3]);
            mma_bf16(acc[mt][2], al[mt], bh[1][0], bh[1][2]);
            mma_bf16(acc[mt][3], al[mt], bh[1][1], bh[1][3]);
        }
    }

    // Epilogue: out = exp2(min(cross*L2E - hx', 0 shifted) ... folded form:
    //   exp2(min(cross*L2E - hx' - hy', lv)),  hx' = hx*L2E - lv, hy' = hy*L2E
    const int g = lane >> 2;
    const int n2 = (lane & 3) * 2;
    const float* HX = (const float*)(smem + SMEM_HX);
    const float* HY = (const float*)(smem + SMEM_HY);

    #pragma unroll
    for (int mt = 0; mt < 4; mt++) {
        const int r0 = mbase + mt * 16 + g;
        const float hx0 = HX[r0];
        const float hx1 = HX[r0 + 8];
        #pragma unroll
        for (int nt = 0; nt < 4; nt++) {
            const int cc = nbase + nt * 8 + n2;
            const float hy0 = HY[cc];
            const float hy1 = HY[cc + 1];
            float* c = acc[mt][nt];
            float2 o0, o1;
            o0.x = fexp2(fminf(fmaf(c[0], L2E, -hx0) - hy0, lv));
            o0.y = fexp2(fminf(fmaf(c[1], L2E, -hx0) - hy1, lv));
            o1.x = fexp2(fminf(fmaf(c[2], L2E, -hx1) - hy0, lv));
            o1.y = fexp2(fminf(fmaf(c[3], L2E, -hx1) - hy1, lv));
            *(float2*)(out + (size_t)(x0 + r0) * MROWS + y0 + cc)     = o0;
            *(float2*)(out + (size_t)(x0 + r0 + 8) * MROWS + y0 + cc) = o1;
        }
    }
}

// ---------------------------------------------------------------------------
extern "C" void kernel_launch(void* const* d_in, const int* in_sizes, int n_in,
                              void* d_out, int out_size) {
    const float* X   = (const float*)d_in[0];
    const float* X2  = (const float*)d_in[1];
    const float* ls  = (const float*)d_in[2];
    const float* var = (const float*)d_in[3];
    float* out = (float*)d_out;

    prep_kernel<<<256, 256>>>(X, X2, ls, var);

    cudaFuncSetAttribute(rbf_mma_kernel,
                         cudaFuncAttributeMaxDynamicSharedMemorySize, SMEM_TOTAL);
    dim3 grid(MROWS / 128, NROWS / 128);
    rbf_mma_kernel<<<grid, 256, SMEM_TOTAL>>>(out);
}